// round 7
// baseline (speedup 1.0000x reference)
#include <cuda_runtime.h>
#include <cuda_bf16.h>
#include <cuda_fp16.h>
#include <math.h>
#include <stdint.h>

#define N_NODES  50000
#define N_EDGES  800000
#define E_TOT    850000
#define N_GRAPHS 64
#define D        128
#define N_CLASSES 10
#define NEG_SLOPE 0.2f
#define N_LAYERS 5

// ----------------------------- scratch (device globals) --------------------
__device__ __half g_xl_h[N_NODES * D];      // fp16 xl (gather stream)
__device__ float  g_xr  [N_NODES * D];
__device__ __nv_bfloat16 g_in_hi[N_NODES * D];
__device__ __nv_bfloat16 g_in_lo[N_NODES * D];
// W fragments in per-lane mma register layout: [l2][k0][jp][lane] -> uint4
__device__ uint4 g_wfrag_hi[N_LAYERS * 2 * 8 * 8 * 32];
__device__ uint4 g_wfrag_lo[N_LAYERS * 2 * 8 * 8 * 32];
__device__ int   g_deg[N_NODES];            // zero-init at load; scan resets to 0
__device__ int   g_off[N_NODES + 1];
__device__ int   g_cur[N_NODES];
__device__ int   g_srcs[E_TOT];
__device__ float g_psum[N_GRAPHS * D];
__device__ int   g_pcnt[N_GRAPHS];
__device__ int   g_flag;                    // scan-done flag (reset in k_prep)

__device__ __forceinline__ float lrelu(float v) { return v > 0.f ? v : NEG_SLOPE * v; }
__device__ __forceinline__ float elu(float v)   { return v > 0.f ? v : __expf(v) - 1.f; }

__device__ __forceinline__ uint32_t smem_u32(const void* p) {
    uint32_t a;
    asm("{ .reg .u64 t; cvta.to.shared.u64 t, %1; cvt.u32.u64 %0, t; }" : "=r"(a) : "l"(p));
    return a;
}

#define LDSM_X4(R, addr) \
    asm volatile("ldmatrix.sync.aligned.m8n8.x4.shared.b16 {%0,%1,%2,%3}, [%4];" \
        : "=r"((R)[0]), "=r"((R)[1]), "=r"((R)[2]), "=r"((R)[3]) : "r"(addr))
#define MMA_BF16(C, A, B0, B1) \
    asm volatile("mma.sync.aligned.m16n8k16.row.col.f32.bf16.bf16.f32 " \
        "{%0,%1,%2,%3}, {%4,%5,%6,%7}, {%8,%9}, {%0,%1,%2,%3};" \
        : "+f"((C)[0]), "+f"((C)[1]), "+f"((C)[2]), "+f"((C)[3]) \
        : "r"((A)[0]), "r"((A)[1]), "r"((A)[2]), "r"((A)[3]), "r"(B0), "r"(B1))

// ----------------------------- fused prep -----------------------------------
__global__ void k_prep(const float* __restrict__ x, const int* __restrict__ ei,
                       const float* __restrict__ Wl, const float* __restrict__ Wr) {
    int i = blockIdx.x * blockDim.x + threadIdx.x;

    if (i == 0) g_flag = 0;

    if (i < N_NODES * D / 4) {               // bf16-split of input x
        float4 v = ((const float4*)x)[i];
        __nv_bfloat16 h[4], l[4];
        float vv[4] = {v.x, v.y, v.z, v.w};
        #pragma unroll
        for (int j = 0; j < 4; j++) {
            h[j] = __float2bfloat16(vv[j]);
            l[j] = __float2bfloat16(vv[j] - __bfloat162float(h[j]));
        }
        ((uint2*)g_in_hi)[i] = *(const uint2*)h;
        ((uint2*)g_in_lo)[i] = *(const uint2*)l;
    }
    if (i < N_EDGES) atomicAdd(&g_deg[ei[N_EDGES + i]], 1);

    // W fragments: i in [0, 20480): lane|jp|k0|l2
    if (i < N_LAYERS * 2 * 8 * 8 * 32) {
        int lane = i & 31;
        int jp   = (i >> 5) & 7;
        int k0   = (i >> 8) & 7;
        int l2   = i >> 11;
        const float* W = ((l2 & 1) ? Wr : Wl) + (l2 >> 1) * D * D;
        uint32_t hi4[4], lo4[4];
        #pragma unroll
        for (int mi = 0; mi < 4; mi++) {
            int n = jp * 16 + (mi >> 1) * 8 + (lane >> 2);
            int k = k0 * 16 + (mi & 1) * 8 + 2 * (lane & 3);
            float v0 = W[k * D + n], v1 = W[(k + 1) * D + n];
            __nv_bfloat16 h0 = __float2bfloat16(v0);
            __nv_bfloat16 h1 = __float2bfloat16(v1);
            __nv_bfloat16 q0 = __float2bfloat16(v0 - __bfloat162float(h0));
            __nv_bfloat16 q1 = __float2bfloat16(v1 - __bfloat162float(h1));
            __nv_bfloat162 ph = __nv_bfloat162(h0, h1);
            __nv_bfloat162 pl = __nv_bfloat162(q0, q1);
            hi4[mi] = *(uint32_t*)&ph;
            lo4[mi] = *(uint32_t*)&pl;
        }
        g_wfrag_hi[i] = make_uint4(hi4[0], hi4[1], hi4[2], hi4[3]);
        g_wfrag_lo[i] = make_uint4(lo4[0], lo4[1], lo4[2], lo4[3]);
    }
    if (i < N_GRAPHS * D) g_psum[i] = 0.f;
    if (i < N_GRAPHS) g_pcnt[i] = 0;
}

// ---------------- fused scan + fill (block 0 scans, others spin) ------------
__global__ void k_fillscan(const int* __restrict__ ei) {
    if (blockIdx.x == 0) {
        __shared__ int sh[256];
        const int CH = (N_NODES + 255) / 256;       // 196
        int t = threadIdx.x;
        int b0 = t * CH, b1 = min(b0 + CH, N_NODES);
        int s = 0;
        for (int i = b0; i < b1; i++) s += g_deg[i] + 1;   // +1 self loop
        sh[t] = s;
        __syncthreads();
        #pragma unroll
        for (int off = 1; off < 256; off <<= 1) {
            int add = (t >= off) ? sh[t - off] : 0;
            __syncthreads();
            sh[t] += add;
            __syncthreads();
        }
        int run = sh[t] - s;
        for (int i = b0; i < b1; i++) {
            g_off[i] = run; g_cur[i] = run;
            run += g_deg[i] + 1;
            g_deg[i] = 0;                            // ready for next replay
        }
        if (t == 255) g_off[N_NODES] = run;
        __threadfence();
        __syncthreads();
        if (t == 0) atomicExch(&g_flag, 1);
    } else {
        if (threadIdx.x == 0) {
            while (atomicAdd(&g_flag, 0) == 0) __nanosleep(128);
        }
        __syncthreads();
    }
    // fill
    int e = blockIdx.x * blockDim.x + threadIdx.x;
    if (e >= E_TOT) return;
    int s2, d;
    if (e < N_EDGES) { s2 = ei[e]; d = ei[N_EDGES + e]; }
    else             { s2 = d = e - N_EDGES; }
    int pos = atomicAdd(&g_cur[d], 1);
    g_srcs[pos] = s2;
}

// ----------------------------- mma.sync bf16-split GEMM --------------------
// blockIdx.y: 0 -> xl (fp16 out) ; 1 -> xr (fp32 out)
// 2 N-passes of 64 cols each (acc 32 regs) -> 3 CTAs/SM.
#define TSTRIDE 272
#define TBYTES  (128 * TSTRIDE)
#define GSM_TOTAL (2 * TBYTES)

__global__ void __launch_bounds__(256, 3) k_gemm_mma(
    int layer, const float* __restrict__ bl, const float* __restrict__ br)
{
    extern __shared__ char smem[];
    const int tid = threadIdx.x, wid = tid >> 5, lane = tid & 31;
    const int m0 = blockIdx.x * 128;
    const int which = blockIdx.y;

    const uint4* ahi4 = (const uint4*)g_in_hi;
    const uint4* alo4 = (const uint4*)g_in_lo;
    for (int c = tid; c < 2048; c += 256) {
        int row = c >> 4, cb = c & 15;
        int gr = m0 + row;
        uint4 vh = make_uint4(0, 0, 0, 0), vl = make_uint4(0, 0, 0, 0);
        if (gr < N_NODES) { vh = ahi4[gr * 16 + cb]; vl = alo4[gr * 16 + cb]; }
        *(uint4*)(smem + row * TSTRIDE + cb * 16) = vh;
        *(uint4*)(smem + TBYTES + row * TSTRIDE + cb * 16) = vl;
    }
    __syncthreads();

    uint32_t sb = smem_u32(smem);
    uint32_t Ahi = sb, Alo = sb + TBYTES;

    const int wrow = wid * 16;
    uint32_t a_off = (uint32_t)((wrow + (lane & 7) + ((lane >> 3) & 1) * 8) * TSTRIDE
                                + (lane >> 4) * 16);

    const uint4* whp = g_wfrag_hi + (size_t)(layer * 2 + which) * 64 * 32 + lane;
    const uint4* wlp = g_wfrag_lo + (size_t)(layer * 2 + which) * 64 * 32 + lane;

    const float* bias = which ? br : bl;
    int r = lane >> 2, c2 = (lane & 3) * 2;
    int row0 = m0 + wrow + r, row1 = row0 + 8;

    #pragma unroll
    for (int pass = 0; pass < 2; pass++) {
        float acc[8][4];
        #pragma unroll
        for (int j = 0; j < 8; j++)
            #pragma unroll
            for (int q = 0; q < 4; q++) acc[j][q] = 0.f;

        #pragma unroll
        for (int k0 = 0; k0 < 8; k0++) {
            uint32_t ah[4], al[4];
            LDSM_X4(ah, Ahi + a_off + k0 * 32);
            LDSM_X4(al, Alo + a_off + k0 * 32);
            #pragma unroll
            for (int jq = 0; jq < 4; jq++) {
                int jp = pass * 4 + jq;
                uint4 bh = whp[(k0 * 8 + jp) * 32];
                uint4 bo = wlp[(k0 * 8 + jp) * 32];
                MMA_BF16(acc[2 * jq],     ah, bh.x, bh.y);
                MMA_BF16(acc[2 * jq + 1], ah, bh.z, bh.w);
                MMA_BF16(acc[2 * jq],     ah, bo.x, bo.y);
                MMA_BF16(acc[2 * jq + 1], ah, bo.z, bo.w);
                MMA_BF16(acc[2 * jq],     al, bh.x, bh.y);
                MMA_BF16(acc[2 * jq + 1], al, bh.z, bh.w);
            }
        }

        if (which == 0) {                    // fp16 xl
            #pragma unroll
            for (int j = 0; j < 8; j++) {
                int col = pass * 64 + j * 8 + c2;
                float b0v = bias[col], b1v = bias[col + 1];
                if (row0 < N_NODES)
                    *(__half2*)(g_xl_h + (size_t)row0 * D + col) =
                        __floats2half2_rn(acc[j][0] + b0v, acc[j][1] + b1v);
                if (row1 < N_NODES)
                    *(__half2*)(g_xl_h + (size_t)row1 * D + col) =
                        __floats2half2_rn(acc[j][2] + b0v, acc[j][3] + b1v);
            }
        } else {                             // fp32 xr
            #pragma unroll
            for (int j = 0; j < 8; j++) {
                int col = pass * 64 + j * 8 + c2;
                float b0v = bias[col], b1v = bias[col + 1];
                if (row0 < N_NODES)
                    *(float2*)(g_xr + (size_t)row0 * D + col) = make_float2(acc[j][0] + b0v, acc[j][1] + b1v);
                if (row1 < N_NODES)
                    *(float2*)(g_xr + (size_t)row1 * D + col) = make_float2(acc[j][2] + b0v, acc[j][3] + b1v);
            }
        }
    }
}

// --------------- fused edge phase: pipelined gathers, fused pool ------------
__device__ __forceinline__ float4 h4_to_f4(uint2 u) {
    float2 a = __half22float2(*(__half2*)&u.x);
    float2 b = __half22float2(*(__half2*)&u.y);
    return make_float4(a.x, a.y, b.x, b.y);
}

__global__ void __launch_bounds__(256) k_aggregate(
    const float* __restrict__ att, const float* __restrict__ bias,
    const int* __restrict__ batch, int last)
{
    int gid  = (blockIdx.x * blockDim.x + threadIdx.x) >> 5;
    int lane = threadIdx.x & 31;
    if (gid >= N_NODES) return;

    const uint2* __restrict__ xl2 = (const uint2*)g_xl_h;
    float4 xr_v = ((const float4*)g_xr)[gid * 32 + lane];
    float4 a    = ((const float4*)att)[lane];

    int beg = g_off[gid];
    int end = g_off[gid + 1];

    float m = -INFINITY, s = 0.f;
    float ax = 0.f, ay = 0.f, az = 0.f, aw = 0.f;

    // prime first group (clamped indices; tail masked in compute)
    uint2 r0, r1, r2, r3;
    {
        int le = end - 1;
        int i0 = g_srcs[beg];
        int i1 = g_srcs[min(beg + 1, le)];
        int i2 = g_srcs[min(beg + 2, le)];
        int i3 = g_srcs[min(beg + 3, le)];
        r0 = __ldg(&xl2[i0 * 32 + lane]);
        r1 = __ldg(&xl2[i1 * 32 + lane]);
        r2 = __ldg(&xl2[i2 * 32 + lane]);
        r3 = __ldg(&xl2[i3 * 32 + lane]);
    }

    for (int base = beg; base < end; base += 4) {
        uint2 c0 = r0, c1 = r1, c2 = r2, c3 = r3;
        int nb = base + 4;
        if (nb < end) {                      // prefetch next group
            int le = end - 1;
            int i0 = g_srcs[nb];
            int i1 = g_srcs[min(nb + 1, le)];
            int i2 = g_srcs[min(nb + 2, le)];
            int i3 = g_srcs[min(nb + 3, le)];
            r0 = __ldg(&xl2[i0 * 32 + lane]);
            r1 = __ldg(&xl2[i1 * 32 + lane]);
            r2 = __ldg(&xl2[i2 * 32 + lane]);
            r3 = __ldg(&xl2[i3 * 32 + lane]);
        }
        float4 x0 = h4_to_f4(c0);
        float4 x1 = h4_to_f4(c1);
        float4 x2 = h4_to_f4(c2);
        float4 x3 = h4_to_f4(c3);
        float p0 = lrelu(x0.x + xr_v.x) * a.x + lrelu(x0.y + xr_v.y) * a.y +
                   lrelu(x0.z + xr_v.z) * a.z + lrelu(x0.w + xr_v.w) * a.w;
        float p1 = lrelu(x1.x + xr_v.x) * a.x + lrelu(x1.y + xr_v.y) * a.y +
                   lrelu(x1.z + xr_v.z) * a.z + lrelu(x1.w + xr_v.w) * a.w;
        float p2 = lrelu(x2.x + xr_v.x) * a.x + lrelu(x2.y + xr_v.y) * a.y +
                   lrelu(x2.z + xr_v.z) * a.z + lrelu(x2.w + xr_v.w) * a.w;
        float p3 = lrelu(x3.x + xr_v.x) * a.x + lrelu(x3.y + xr_v.y) * a.y +
                   lrelu(x3.z + xr_v.z) * a.z + lrelu(x3.w + xr_v.w) * a.w;
        p0 += __shfl_xor_sync(0xffffffffu, p0, 1);
        p1 += __shfl_xor_sync(0xffffffffu, p1, 1);
        p2 += __shfl_xor_sync(0xffffffffu, p2, 1);
        p3 += __shfl_xor_sync(0xffffffffu, p3, 1);
        p0 += __shfl_xor_sync(0xffffffffu, p0, 2);
        p1 += __shfl_xor_sync(0xffffffffu, p1, 2);
        p2 += __shfl_xor_sync(0xffffffffu, p2, 2);
        p3 += __shfl_xor_sync(0xffffffffu, p3, 2);
        p1 = (base + 1 < end) ? p1 : -INFINITY;   // mask padded tail
        p2 = (base + 2 < end) ? p2 : -INFINITY;
        p3 = (base + 3 < end) ? p3 : -INFINITY;
        float mn = fmaxf(fmaxf(m, fmaxf(p0, p1)), fmaxf(p2, p3));
        float sc = __expf(m - mn);
        float w0 = __expf(p0 - mn);
        float w1 = __expf(p1 - mn);
        float w2 = __expf(p2 - mn);
        float w3 = __expf(p3 - mn);
        s  = s * sc + (w0 + w1) + (w2 + w3);
        ax = ax * sc + (x0.x * w0 + x1.x * w1) + (x2.x * w2 + x3.x * w3);
        ay = ay * sc + (x0.y * w0 + x1.y * w1) + (x2.y * w2 + x3.y * w3);
        az = az * sc + (x0.z * w0 + x1.z * w1) + (x2.z * w2 + x3.z * w3);
        aw = aw * sc + (x0.w * w0 + x1.w * w1) + (x2.w * w2 + x3.w * w3);
        m = mn;
    }

    float inv = 1.f / s;
    float4 bv = ((const float4*)bias)[lane];
    float4 o;
    o.x = elu(ax * inv + bv.x);
    o.y = elu(ay * inv + bv.y);
    o.z = elu(az * inv + bv.z);
    o.w = elu(aw * inv + bv.w);

    if (!last) {                             // feed next layer's GEMM
        __nv_bfloat16 h[4], l[4];
        float vv[4] = {o.x, o.y, o.z, o.w};
        #pragma unroll
        for (int j = 0; j < 4; j++) {
            h[j] = __float2bfloat16(vv[j]);
            l[j] = __float2bfloat16(vv[j] - __bfloat162float(h[j]));
        }
        ((uint2*)g_in_hi)[gid * 32 + lane] = *(const uint2*)h;
        ((uint2*)g_in_lo)[gid * 32 + lane] = *(const uint2*)l;
    } else {                                 // fused global mean pool (sum part)
        int g = batch[gid];
        float* ps = &g_psum[g * D + lane * 4];
        atomicAdd(ps + 0, o.x);
        atomicAdd(ps + 1, o.y);
        atomicAdd(ps + 2, o.z);
        atomicAdd(ps + 3, o.w);
        if (lane == 0) atomicAdd(&g_pcnt[g], 1);
    }
}

// ----------------------------- classifier -----------------------------------
__global__ void k_head(const float* __restrict__ Wout, const float* __restrict__ bout,
                       float* __restrict__ out) {
    int g = threadIdx.x;
    if (g >= N_GRAPHS) return;
    float inv = 1.f / fmaxf((float)g_pcnt[g], 1.f);
    float lg[N_CLASSES];
    #pragma unroll
    for (int c = 0; c < N_CLASSES; c++) lg[c] = bout[c];
    for (int d = 0; d < D; d++) {
        float pv = g_psum[g * D + d] * inv;
        #pragma unroll
        for (int c = 0; c < N_CLASSES; c++)
            lg[c] = fmaf(pv, Wout[d * N_CLASSES + c], lg[c]);
    }
    float mx = lg[0];
    #pragma unroll
    for (int c = 1; c < N_CLASSES; c++) mx = fmaxf(mx, lg[c]);
    float sum = 0.f;
    #pragma unroll
    for (int c = 0; c < N_CLASSES; c++) sum += expf(lg[c] - mx);
    float ls = logf(sum);
    #pragma unroll
    for (int c = 0; c < N_CLASSES; c++) out[g * N_CLASSES + c] = lg[c] - mx - ls;
}

// ----------------------------- launch --------------------------------------
extern "C" void kernel_launch(void* const* d_in, const int* in_sizes, int n_in,
                              void* d_out, int out_size) {
    const float* x    = (const float*)d_in[0];
    const int*   ei   = (const int*)d_in[1];
    const int*   batch= (const int*)d_in[2];
    const float* Wl   = (const float*)d_in[3];
    const float* bl   = (const float*)d_in[4];
    const float* Wr   = (const float*)d_in[5];
    const float* brp  = (const float*)d_in[6];
    const float* att  = (const float*)d_in[7];
    const float* bias = (const float*)d_in[8];
    const float* Wout = (const float*)d_in[9];
    const float* bout = (const float*)d_in[10];
    float* out = (float*)d_out;

    cudaFuncSetAttribute(k_gemm_mma, cudaFuncAttributeMaxDynamicSharedMemorySize, GSM_TOTAL);

    k_prep<<<(N_NODES * D / 4 + 255) / 256, 256>>>(x, ei, Wl, Wr);        // #1
    k_fillscan<<<(E_TOT + 255) / 256, 256>>>(ei);                         // #2

    dim3 gemm_grid((N_NODES + 127) / 128, 2);
    const int agg_blocks = (N_NODES * 32 + 255) / 256;

    for (int l = 0; l < N_LAYERS; l++) {
        k_gemm_mma<<<gemm_grid, 256, GSM_TOTAL>>>(l, bl + l * D, brp + l * D);  // #3,5,7,9,11
        k_aggregate<<<agg_blocks, 256>>>(att + l * D, bias + l * D, batch,
                                         l == N_LAYERS - 1);                    // #4(profiled),6,...
    }

    k_head<<<1, 64>>>(Wout, bout, out);
}

// round 8
// speedup vs baseline: 1.0944x; 1.0944x over previous
#include <cuda_runtime.h>
#include <cuda_bf16.h>
#include <cuda_fp16.h>
#include <math.h>
#include <stdint.h>

#define N_NODES  50000
#define N_EDGES  800000
#define E_TOT    850000
#define N_GRAPHS 64
#define D        128
#define N_CLASSES 10
#define NEG_SLOPE 0.2f
#define N_LAYERS 5

// ----------------------------- scratch (device globals) --------------------
__device__ __half g_xl_h[N_NODES * D];      // fp16 xl (gather stream)
__device__ float  g_xr  [N_NODES * D];
__device__ __nv_bfloat16 g_in_hi[N_NODES * D];
__device__ __nv_bfloat16 g_in_lo[N_NODES * D];
// W fragments in per-lane mma register layout: [l2][k0][jp][lane] -> uint4
__device__ uint4 g_wfrag_hi[N_LAYERS * 2 * 8 * 8 * 32];
__device__ uint4 g_wfrag_lo[N_LAYERS * 2 * 8 * 8 * 32];
__device__ int   g_deg[N_NODES];            // zero-init at load; scan resets to 0
__device__ int   g_off[N_NODES + 1];
__device__ int   g_cur[N_NODES];
__device__ int   g_srcs[E_TOT];
__device__ float g_psum[N_GRAPHS * D];
__device__ int   g_pcnt[N_GRAPHS];

__device__ __forceinline__ float lrelu(float v) { return v > 0.f ? v : NEG_SLOPE * v; }
__device__ __forceinline__ float elu(float v)   { return v > 0.f ? v : __expf(v) - 1.f; }

__device__ __forceinline__ uint32_t smem_u32(const void* p) {
    uint32_t a;
    asm("{ .reg .u64 t; cvta.to.shared.u64 t, %1; cvt.u32.u64 %0, t; }" : "=r"(a) : "l"(p));
    return a;
}

#define LDSM_X4(R, addr) \
    asm volatile("ldmatrix.sync.aligned.m8n8.x4.shared.b16 {%0,%1,%2,%3}, [%4];" \
        : "=r"((R)[0]), "=r"((R)[1]), "=r"((R)[2]), "=r"((R)[3]) : "r"(addr))
#define MMA_BF16(C, A, B0, B1) \
    asm volatile("mma.sync.aligned.m16n8k16.row.col.f32.bf16.bf16.f32 " \
        "{%0,%1,%2,%3}, {%4,%5,%6,%7}, {%8,%9}, {%0,%1,%2,%3};" \
        : "+f"((C)[0]), "+f"((C)[1]), "+f"((C)[2]), "+f"((C)[3]) \
        : "r"((A)[0]), "r"((A)[1]), "r"((A)[2]), "r"((A)[3]), "r"(B0), "r"(B1))

// ----------------------------- fused prep -----------------------------------
__global__ void k_prep(const float* __restrict__ x, const int* __restrict__ ei,
                       const float* __restrict__ Wl, const float* __restrict__ Wr) {
    int i = blockIdx.x * blockDim.x + threadIdx.x;

    if (i < N_NODES * D / 4) {               // bf16-split of input x
        float4 v = ((const float4*)x)[i];
        __nv_bfloat16 h[4], l[4];
        float vv[4] = {v.x, v.y, v.z, v.w};
        #pragma unroll
        for (int j = 0; j < 4; j++) {
            h[j] = __float2bfloat16(vv[j]);
            l[j] = __float2bfloat16(vv[j] - __bfloat162float(h[j]));
        }
        ((uint2*)g_in_hi)[i] = *(const uint2*)h;
        ((uint2*)g_in_lo)[i] = *(const uint2*)l;
    }
    if (i < N_EDGES) atomicAdd(&g_deg[ei[N_EDGES + i]], 1);

    // W fragments: i in [0, 20480): lane|jp|k0|l2
    if (i < N_LAYERS * 2 * 8 * 8 * 32) {
        int lane = i & 31;
        int jp   = (i >> 5) & 7;
        int k0   = (i >> 8) & 7;
        int l2   = i >> 11;
        const float* W = ((l2 & 1) ? Wr : Wl) + (l2 >> 1) * D * D;
        uint32_t hi4[4], lo4[4];
        #pragma unroll
        for (int mi = 0; mi < 4; mi++) {
            int n = jp * 16 + (mi >> 1) * 8 + (lane >> 2);
            int k = k0 * 16 + (mi & 1) * 8 + 2 * (lane & 3);
            float v0 = W[k * D + n], v1 = W[(k + 1) * D + n];
            __nv_bfloat16 h0 = __float2bfloat16(v0);
            __nv_bfloat16 h1 = __float2bfloat16(v1);
            __nv_bfloat16 q0 = __float2bfloat16(v0 - __bfloat162float(h0));
            __nv_bfloat16 q1 = __float2bfloat16(v1 - __bfloat162float(h1));
            __nv_bfloat162 ph = __nv_bfloat162(h0, h1);
            __nv_bfloat162 pl = __nv_bfloat162(q0, q1);
            hi4[mi] = *(uint32_t*)&ph;
            lo4[mi] = *(uint32_t*)&pl;
        }
        g_wfrag_hi[i] = make_uint4(hi4[0], hi4[1], hi4[2], hi4[3]);
        g_wfrag_lo[i] = make_uint4(lo4[0], lo4[1], lo4[2], lo4[3]);
    }
    if (i < N_GRAPHS * D) g_psum[i] = 0.f;
    if (i < N_GRAPHS) g_pcnt[i] = 0;
}

// single-block scan; degree = g_deg + 1 (self loop); resets g_deg for next replay
__global__ void k_scan() {
    __shared__ int sh[1024];
    const int CH = (N_NODES + 1023) / 1024;
    int t = threadIdx.x;
    int beg = t * CH, end = min(beg + CH, N_NODES);
    int s = 0;
    for (int i = beg; i < end; i++) s += g_deg[i] + 1;
    sh[t] = s;
    __syncthreads();
    #pragma unroll
    for (int off = 1; off < 1024; off <<= 1) {
        int add = (t >= off) ? sh[t - off] : 0;
        __syncthreads();
        sh[t] += add;
        __syncthreads();
    }
    int run = sh[t] - s;
    for (int i = beg; i < end; i++) {
        g_off[i] = run; g_cur[i] = run;
        run += g_deg[i] + 1;
        g_deg[i] = 0;
    }
    if (t == 1023) g_off[N_NODES] = run;
}

__global__ void k_fill(const int* __restrict__ ei) {
    int e = blockIdx.x * blockDim.x + threadIdx.x;
    if (e >= E_TOT) return;
    int s, d;
    if (e < N_EDGES) { s = ei[e]; d = ei[N_EDGES + e]; }
    else             { s = d = e - N_EDGES; }
    int pos = atomicAdd(&g_cur[d], 1);
    g_srcs[pos] = s;
}

// ----------------------------- mma.sync bf16-split GEMM --------------------
// blockIdx.y: 0 -> xl (fp16 out) ; 1 -> xr (fp32 out)
// Round-6 config: single N-pass, 2 CTAs/SM, 128 regs (no spills).
#define TSTRIDE 272
#define TBYTES  (128 * TSTRIDE)
#define GSM_TOTAL (2 * TBYTES)

__global__ void __launch_bounds__(256, 2) k_gemm_mma(
    int layer, const float* __restrict__ bl, const float* __restrict__ br)
{
    extern __shared__ char smem[];
    const int tid = threadIdx.x, wid = tid >> 5, lane = tid & 31;
    const int m0 = blockIdx.x * 128;
    const int which = blockIdx.y;

    const uint4* ahi4 = (const uint4*)g_in_hi;
    const uint4* alo4 = (const uint4*)g_in_lo;
    for (int c = tid; c < 2048; c += 256) {
        int row = c >> 4, cb = c & 15;
        int gr = m0 + row;
        uint4 vh = make_uint4(0, 0, 0, 0), vl = make_uint4(0, 0, 0, 0);
        if (gr < N_NODES) { vh = ahi4[gr * 16 + cb]; vl = alo4[gr * 16 + cb]; }
        *(uint4*)(smem + row * TSTRIDE + cb * 16) = vh;
        *(uint4*)(smem + TBYTES + row * TSTRIDE + cb * 16) = vl;
    }
    __syncthreads();

    uint32_t sb = smem_u32(smem);
    uint32_t Ahi = sb, Alo = sb + TBYTES;

    float acc[16][4];
    #pragma unroll
    for (int j = 0; j < 16; j++)
        #pragma unroll
        for (int q = 0; q < 4; q++) acc[j][q] = 0.f;

    const int wrow = wid * 16;
    uint32_t a_off = (uint32_t)((wrow + (lane & 7) + ((lane >> 3) & 1) * 8) * TSTRIDE
                                + (lane >> 4) * 16);

    const uint4* whp = g_wfrag_hi + (size_t)(layer * 2 + which) * 64 * 32 + lane;
    const uint4* wlp = g_wfrag_lo + (size_t)(layer * 2 + which) * 64 * 32 + lane;

    #pragma unroll
    for (int k0 = 0; k0 < 8; k0++) {
        uint32_t ah[4], al[4];
        LDSM_X4(ah, Ahi + a_off + k0 * 32);
        LDSM_X4(al, Alo + a_off + k0 * 32);
        #pragma unroll
        for (int jp = 0; jp < 8; jp++) {
            uint4 bh = whp[(k0 * 8 + jp) * 32];
            uint4 bo = wlp[(k0 * 8 + jp) * 32];
            MMA_BF16(acc[2 * jp],     ah, bh.x, bh.y);
            MMA_BF16(acc[2 * jp + 1], ah, bh.z, bh.w);
            MMA_BF16(acc[2 * jp],     ah, bo.x, bo.y);
            MMA_BF16(acc[2 * jp + 1], ah, bo.z, bo.w);
            MMA_BF16(acc[2 * jp],     al, bh.x, bh.y);
            MMA_BF16(acc[2 * jp + 1], al, bh.z, bh.w);
        }
    }

    const float* bias = which ? br : bl;
    int r = lane >> 2, c2 = (lane & 3) * 2;
    int row0 = m0 + wrow + r, row1 = row0 + 8;
    if (which == 0) {                        // fp16 xl
        #pragma unroll
        for (int j = 0; j < 16; j++) {
            int col = j * 8 + c2;
            float b0v = bias[col], b1v = bias[col + 1];
            if (row0 < N_NODES)
                *(__half2*)(g_xl_h + (size_t)row0 * D + col) =
                    __floats2half2_rn(acc[j][0] + b0v, acc[j][1] + b1v);
            if (row1 < N_NODES)
                *(__half2*)(g_xl_h + (size_t)row1 * D + col) =
                    __floats2half2_rn(acc[j][2] + b0v, acc[j][3] + b1v);
        }
    } else {                                 // fp32 xr
        #pragma unroll
        for (int j = 0; j < 16; j++) {
            int col = j * 8 + c2;
            float b0v = bias[col], b1v = bias[col + 1];
            if (row0 < N_NODES)
                *(float2*)(g_xr + (size_t)row0 * D + col) = make_float2(acc[j][0] + b0v, acc[j][1] + b1v);
            if (row1 < N_NODES)
                *(float2*)(g_xr + (size_t)row1 * D + col) = make_float2(acc[j][2] + b0v, acc[j][3] + b1v);
        }
    }
}

// --------------- fused edge phase: pipelined gathers, fused pool ------------
__device__ __forceinline__ float4 h4_to_f4(uint2 u) {
    float2 a = __half22float2(*(__half2*)&u.x);
    float2 b = __half22float2(*(__half2*)&u.y);
    return make_float4(a.x, a.y, b.x, b.y);
}

__global__ void __launch_bounds__(256) k_aggregate(
    const float* __restrict__ att, const float* __restrict__ bias,
    const int* __restrict__ batch, int last)
{
    int gid  = (blockIdx.x * blockDim.x + threadIdx.x) >> 5;
    int lane = threadIdx.x & 31;
    if (gid >= N_NODES) return;

    const uint2* __restrict__ xl2 = (const uint2*)g_xl_h;
    float4 xr_v = ((const float4*)g_xr)[gid * 32 + lane];
    float4 a    = ((const float4*)att)[lane];

    int beg = g_off[gid];
    int end = g_off[gid + 1];

    float m = -INFINITY, s = 0.f;
    float ax = 0.f, ay = 0.f, az = 0.f, aw = 0.f;

    // prime first group (clamped indices; tail masked in compute)
    uint2 r0, r1, r2, r3;
    {
        int le = end - 1;
        int i0 = g_srcs[beg];
        int i1 = g_srcs[min(beg + 1, le)];
        int i2 = g_srcs[min(beg + 2, le)];
        int i3 = g_srcs[min(beg + 3, le)];
        r0 = __ldg(&xl2[i0 * 32 + lane]);
        r1 = __ldg(&xl2[i1 * 32 + lane]);
        r2 = __ldg(&xl2[i2 * 32 + lane]);
        r3 = __ldg(&xl2[i3 * 32 + lane]);
    }

    for (int base = beg; base < end; base += 4) {
        uint2 c0 = r0, c1 = r1, c2 = r2, c3 = r3;
        int nb = base + 4;
        if (nb < end) {                      // prefetch next group
            int le = end - 1;
            int i0 = g_srcs[nb];
            int i1 = g_srcs[min(nb + 1, le)];
            int i2 = g_srcs[min(nb + 2, le)];
            int i3 = g_srcs[min(nb + 3, le)];
            r0 = __ldg(&xl2[i0 * 32 + lane]);
            r1 = __ldg(&xl2[i1 * 32 + lane]);
            r2 = __ldg(&xl2[i2 * 32 + lane]);
            r3 = __ldg(&xl2[i3 * 32 + lane]);
        }
        float4 x0 = h4_to_f4(c0);
        float4 x1 = h4_to_f4(c1);
        float4 x2 = h4_to_f4(c2);
        float4 x3 = h4_to_f4(c3);
        float p0 = lrelu(x0.x + xr_v.x) * a.x + lrelu(x0.y + xr_v.y) * a.y +
                   lrelu(x0.z + xr_v.z) * a.z + lrelu(x0.w + xr_v.w) * a.w;
        float p1 = lrelu(x1.x + xr_v.x) * a.x + lrelu(x1.y + xr_v.y) * a.y +
                   lrelu(x1.z + xr_v.z) * a.z + lrelu(x1.w + xr_v.w) * a.w;
        float p2 = lrelu(x2.x + xr_v.x) * a.x + lrelu(x2.y + xr_v.y) * a.y +
                   lrelu(x2.z + xr_v.z) * a.z + lrelu(x2.w + xr_v.w) * a.w;
        float p3 = lrelu(x3.x + xr_v.x) * a.x + lrelu(x3.y + xr_v.y) * a.y +
                   lrelu(x3.z + xr_v.z) * a.z + lrelu(x3.w + xr_v.w) * a.w;
        p0 += __shfl_xor_sync(0xffffffffu, p0, 1);
        p1 += __shfl_xor_sync(0xffffffffu, p1, 1);
        p2 += __shfl_xor_sync(0xffffffffu, p2, 1);
        p3 += __shfl_xor_sync(0xffffffffu, p3, 1);
        p0 += __shfl_xor_sync(0xffffffffu, p0, 2);
        p1 += __shfl_xor_sync(0xffffffffu, p1, 2);
        p2 += __shfl_xor_sync(0xffffffffu, p2, 2);
        p3 += __shfl_xor_sync(0xffffffffu, p3, 2);
        p1 = (base + 1 < end) ? p1 : -INFINITY;   // mask padded tail
        p2 = (base + 2 < end) ? p2 : -INFINITY;
        p3 = (base + 3 < end) ? p3 : -INFINITY;
        float mn = fmaxf(fmaxf(m, fmaxf(p0, p1)), fmaxf(p2, p3));
        float sc = __expf(m - mn);
        float w0 = __expf(p0 - mn);
        float w1 = __expf(p1 - mn);
        float w2 = __expf(p2 - mn);
        float w3 = __expf(p3 - mn);
        s  = s * sc + (w0 + w1) + (w2 + w3);
        ax = ax * sc + (x0.x * w0 + x1.x * w1) + (x2.x * w2 + x3.x * w3);
        ay = ay * sc + (x0.y * w0 + x1.y * w1) + (x2.y * w2 + x3.y * w3);
        az = az * sc + (x0.z * w0 + x1.z * w1) + (x2.z * w2 + x3.z * w3);
        aw = aw * sc + (x0.w * w0 + x1.w * w1) + (x2.w * w2 + x3.w * w3);
        m = mn;
    }

    float inv = 1.f / s;
    float4 bv = ((const float4*)bias)[lane];
    float4 o;
    o.x = elu(ax * inv + bv.x);
    o.y = elu(ay * inv + bv.y);
    o.z = elu(az * inv + bv.z);
    o.w = elu(aw * inv + bv.w);

    if (!last) {                             // feed next layer's GEMM
        __nv_bfloat16 h[4], l[4];
        float vv[4] = {o.x, o.y, o.z, o.w};
        #pragma unroll
        for (int j = 0; j < 4; j++) {
            h[j] = __float2bfloat16(vv[j]);
            l[j] = __float2bfloat16(vv[j] - __bfloat162float(h[j]));
        }
        ((uint2*)g_in_hi)[gid * 32 + lane] = *(const uint2*)h;
        ((uint2*)g_in_lo)[gid * 32 + lane] = *(const uint2*)l;
    } else {                                 // fused global mean pool (sum part)
        int g = batch[gid];
        float* ps = &g_psum[g * D + lane * 4];
        atomicAdd(ps + 0, o.x);
        atomicAdd(ps + 1, o.y);
        atomicAdd(ps + 2, o.z);
        atomicAdd(ps + 3, o.w);
        if (lane == 0) atomicAdd(&g_pcnt[g], 1);
    }
}

// ----------------------------- classifier -----------------------------------
__global__ void k_head(const float* __restrict__ Wout, const float* __restrict__ bout,
                       float* __restrict__ out) {
    int g = threadIdx.x;
    if (g >= N_GRAPHS) return;
    float inv = 1.f / fmaxf((float)g_pcnt[g], 1.f);
    float lg[N_CLASSES];
    #pragma unroll
    for (int c = 0; c < N_CLASSES; c++) lg[c] = bout[c];
    for (int d = 0; d < D; d++) {
        float pv = g_psum[g * D + d] * inv;
        #pragma unroll
        for (int c = 0; c < N_CLASSES; c++)
            lg[c] = fmaf(pv, Wout[d * N_CLASSES + c], lg[c]);
    }
    float mx = lg[0];
    #pragma unroll
    for (int c = 1; c < N_CLASSES; c++) mx = fmaxf(mx, lg[c]);
    float sum = 0.f;
    #pragma unroll
    for (int c = 0; c < N_CLASSES; c++) sum += expf(lg[c] - mx);
    float ls = logf(sum);
    #pragma unroll
    for (int c = 0; c < N_CLASSES; c++) out[g * N_CLASSES + c] = lg[c] - mx - ls;
}

// ----------------------------- launch --------------------------------------
extern "C" void kernel_launch(void* const* d_in, const int* in_sizes, int n_in,
                              void* d_out, int out_size) {
    const float* x    = (const float*)d_in[0];
    const int*   ei   = (const int*)d_in[1];
    const int*   batch= (const int*)d_in[2];
    const float* Wl   = (const float*)d_in[3];
    const float* bl   = (const float*)d_in[4];
    const float* Wr   = (const float*)d_in[5];
    const float* brp  = (const float*)d_in[6];
    const float* att  = (const float*)d_in[7];
    const float* bias = (const float*)d_in[8];
    const float* Wout = (const float*)d_in[9];
    const float* bout = (const float*)d_in[10];
    float* out = (float*)d_out;

    cudaFuncSetAttribute(k_gemm_mma, cudaFuncAttributeMaxDynamicSharedMemorySize, GSM_TOTAL);

    k_prep<<<(N_NODES * D / 4 + 255) / 256, 256>>>(x, ei, Wl, Wr);   // #1
    k_scan<<<1, 1024>>>();                                           // #2
    k_fill<<<(E_TOT + 255) / 256, 256>>>(ei);                        // #3

    dim3 gemm_grid((N_NODES + 127) / 128, 2);
    const int agg_blocks = (N_NODES * 32 + 255) / 256;

    for (int l = 0; l < N_LAYERS; l++) {
        k_gemm_mma<<<gemm_grid, 256, GSM_TOTAL>>>(l, bl + l * D, brp + l * D);  // #4 profiled
        k_aggregate<<<agg_blocks, 256>>>(att + l * D, bias + l * D, batch,
                                         l == N_LAYERS - 1);
    }

    k_head<<<1, 64>>>(Wout, bout, out);
}

// round 9
// speedup vs baseline: 1.1873x; 1.0848x over previous
#include <cuda_runtime.h>
#include <cuda_bf16.h>
#include <cuda_fp16.h>
#include <math.h>
#include <stdint.h>

#define N_NODES  50000
#define N_EDGES  800000
#define E_TOT    850000
#define N_GRAPHS 64
#define D        128
#define N_CLASSES 10
#define NEG_SLOPE 0.2f
#define N_LAYERS 5

// ----------------------------- scratch (device globals) --------------------
__device__ __half g_xl_h[N_NODES * D];      // fp16 xl (gather stream)
__device__ float  g_xr  [N_NODES * D];
__device__ __nv_bfloat16 g_in_hi[N_NODES * D];
__device__ __nv_bfloat16 g_in_lo[N_NODES * D];
// W fragments in per-lane mma register layout: [l2][k0][jp][lane] -> uint4
__device__ uint4 g_wfrag_hi[N_LAYERS * 2 * 8 * 8 * 32];
__device__ uint4 g_wfrag_lo[N_LAYERS * 2 * 8 * 8 * 32];
__device__ int   g_deg[N_NODES];            // zero-init at load; scan resets to 0
__device__ int   g_off[N_NODES + 1];
__device__ int   g_cur[N_NODES];
__device__ int   g_srcs[E_TOT];
__device__ float g_psum[N_GRAPHS * D];
__device__ int   g_pcnt[N_GRAPHS];

__device__ __forceinline__ float lrelu(float v) { return v > 0.f ? v : NEG_SLOPE * v; }
__device__ __forceinline__ float elu(float v)   { return v > 0.f ? v : __expf(v) - 1.f; }

__device__ __forceinline__ uint32_t smem_u32(const void* p) {
    uint32_t a;
    asm("{ .reg .u64 t; cvta.to.shared.u64 t, %1; cvt.u32.u64 %0, t; }" : "=r"(a) : "l"(p));
    return a;
}

#define LDSM_X4(R, addr) \
    asm volatile("ldmatrix.sync.aligned.m8n8.x4.shared.b16 {%0,%1,%2,%3}, [%4];" \
        : "=r"((R)[0]), "=r"((R)[1]), "=r"((R)[2]), "=r"((R)[3]) : "r"(addr))
#define MMA_BF16(C, A, B0, B1) \
    asm volatile("mma.sync.aligned.m16n8k16.row.col.f32.bf16.bf16.f32 " \
        "{%0,%1,%2,%3}, {%4,%5,%6,%7}, {%8,%9}, {%0,%1,%2,%3};" \
        : "+f"((C)[0]), "+f"((C)[1]), "+f"((C)[2]), "+f"((C)[3]) \
        : "r"((A)[0]), "r"((A)[1]), "r"((A)[2]), "r"((A)[3]), "r"(B0), "r"(B1))

// ----------------------------- fused prep -----------------------------------
__global__ void k_prep(const float* __restrict__ x, const int* __restrict__ ei,
                       const float* __restrict__ Wl, const float* __restrict__ Wr) {
    int i = blockIdx.x * blockDim.x + threadIdx.x;

    if (i < N_NODES * D / 4) {               // bf16-split of input x
        float4 v = ((const float4*)x)[i];
        __nv_bfloat16 h[4], l[4];
        float vv[4] = {v.x, v.y, v.z, v.w};
        #pragma unroll
        for (int j = 0; j < 4; j++) {
            h[j] = __float2bfloat16(vv[j]);
            l[j] = __float2bfloat16(vv[j] - __bfloat162float(h[j]));
        }
        ((uint2*)g_in_hi)[i] = *(const uint2*)h;
        ((uint2*)g_in_lo)[i] = *(const uint2*)l;
    }
    if (i < N_EDGES) atomicAdd(&g_deg[ei[N_EDGES + i]], 1);

    // W fragments: i in [0, 20480): lane|jp|k0|l2
    if (i < N_LAYERS * 2 * 8 * 8 * 32) {
        int lane = i & 31;
        int jp   = (i >> 5) & 7;
        int k0   = (i >> 8) & 7;
        int l2   = i >> 11;
        const float* W = ((l2 & 1) ? Wr : Wl) + (l2 >> 1) * D * D;
        uint32_t hi4[4], lo4[4];
        #pragma unroll
        for (int mi = 0; mi < 4; mi++) {
            int n = jp * 16 + (mi >> 1) * 8 + (lane >> 2);
            int k = k0 * 16 + (mi & 1) * 8 + 2 * (lane & 3);
            float v0 = W[k * D + n], v1 = W[(k + 1) * D + n];
            __nv_bfloat16 h0 = __float2bfloat16(v0);
            __nv_bfloat16 h1 = __float2bfloat16(v1);
            __nv_bfloat16 q0 = __float2bfloat16(v0 - __bfloat162float(h0));
            __nv_bfloat16 q1 = __float2bfloat16(v1 - __bfloat162float(h1));
            __nv_bfloat162 ph = __nv_bfloat162(h0, h1);
            __nv_bfloat162 pl = __nv_bfloat162(q0, q1);
            hi4[mi] = *(uint32_t*)&ph;
            lo4[mi] = *(uint32_t*)&pl;
        }
        g_wfrag_hi[i] = make_uint4(hi4[0], hi4[1], hi4[2], hi4[3]);
        g_wfrag_lo[i] = make_uint4(lo4[0], lo4[1], lo4[2], lo4[3]);
    }
    if (i < N_GRAPHS * D) g_psum[i] = 0.f;
    if (i < N_GRAPHS) g_pcnt[i] = 0;
}

// single-block scan; degree = g_deg + 1 (self loop); resets g_deg for next replay
__global__ void k_scan() {
    __shared__ int sh[1024];
    const int CH = (N_NODES + 1023) / 1024;
    int t = threadIdx.x;
    int beg = t * CH, end = min(beg + CH, N_NODES);
    int s = 0;
    for (int i = beg; i < end; i++) s += g_deg[i] + 1;
    sh[t] = s;
    __syncthreads();
    #pragma unroll
    for (int off = 1; off < 1024; off <<= 1) {
        int add = (t >= off) ? sh[t - off] : 0;
        __syncthreads();
        sh[t] += add;
        __syncthreads();
    }
    int run = sh[t] - s;
    for (int i = beg; i < end; i++) {
        g_off[i] = run; g_cur[i] = run;
        run += g_deg[i] + 1;
        g_deg[i] = 0;
    }
    if (t == 1023) g_off[N_NODES] = run;
}

__global__ void k_fill(const int* __restrict__ ei) {
    int e = blockIdx.x * blockDim.x + threadIdx.x;
    if (e >= E_TOT) return;
    int s, d;
    if (e < N_EDGES) { s = ei[e]; d = ei[N_EDGES + e]; }
    else             { s = d = e - N_EDGES; }
    int pos = atomicAdd(&g_cur[d], 1);
    g_srcs[pos] = s;
}

// ----------------------------- mma.sync bf16-split GEMM --------------------
// blockIdx.y: 0 -> xl (fp16 out) ; 1 -> xr (fp32 out)
// Round-6 config: single N-pass, 2 CTAs/SM, 128 regs (no spills).
#define TSTRIDE 272
#define TBYTES  (128 * TSTRIDE)
#define GSM_TOTAL (2 * TBYTES)

__global__ void __launch_bounds__(256, 2) k_gemm_mma(
    int layer, const float* __restrict__ bl, const float* __restrict__ br)
{
    extern __shared__ char smem[];
    const int tid = threadIdx.x, wid = tid >> 5, lane = tid & 31;
    const int m0 = blockIdx.x * 128;
    const int which = blockIdx.y;

    const uint4* ahi4 = (const uint4*)g_in_hi;
    const uint4* alo4 = (const uint4*)g_in_lo;
    for (int c = tid; c < 2048; c += 256) {
        int row = c >> 4, cb = c & 15;
        int gr = m0 + row;
        uint4 vh = make_uint4(0, 0, 0, 0), vl = make_uint4(0, 0, 0, 0);
        if (gr < N_NODES) { vh = ahi4[gr * 16 + cb]; vl = alo4[gr * 16 + cb]; }
        *(uint4*)(smem + row * TSTRIDE + cb * 16) = vh;
        *(uint4*)(smem + TBYTES + row * TSTRIDE + cb * 16) = vl;
    }
    __syncthreads();

    uint32_t sb = smem_u32(smem);
    uint32_t Ahi = sb, Alo = sb + TBYTES;

    float acc[16][4];
    #pragma unroll
    for (int j = 0; j < 16; j++)
        #pragma unroll
        for (int q = 0; q < 4; q++) acc[j][q] = 0.f;

    const int wrow = wid * 16;
    uint32_t a_off = (uint32_t)((wrow + (lane & 7) + ((lane >> 3) & 1) * 8) * TSTRIDE
                                + (lane >> 4) * 16);

    const uint4* whp = g_wfrag_hi + (size_t)(layer * 2 + which) * 64 * 32 + lane;
    const uint4* wlp = g_wfrag_lo + (size_t)(layer * 2 + which) * 64 * 32 + lane;

    #pragma unroll
    for (int k0 = 0; k0 < 8; k0++) {
        uint32_t ah[4], al[4];
        LDSM_X4(ah, Ahi + a_off + k0 * 32);
        LDSM_X4(al, Alo + a_off + k0 * 32);
        #pragma unroll
        for (int jp = 0; jp < 8; jp++) {
            uint4 bh = whp[(k0 * 8 + jp) * 32];
            uint4 bo = wlp[(k0 * 8 + jp) * 32];
            MMA_BF16(acc[2 * jp],     ah, bh.x, bh.y);
            MMA_BF16(acc[2 * jp + 1], ah, bh.z, bh.w);
            MMA_BF16(acc[2 * jp],     ah, bo.x, bo.y);
            MMA_BF16(acc[2 * jp + 1], ah, bo.z, bo.w);
            MMA_BF16(acc[2 * jp],     al, bh.x, bh.y);
            MMA_BF16(acc[2 * jp + 1], al, bh.z, bh.w);
        }
    }

    const float* bias = which ? br : bl;
    int r = lane >> 2, c2 = (lane & 3) * 2;
    int row0 = m0 + wrow + r, row1 = row0 + 8;
    if (which == 0) {                        // fp16 xl
        #pragma unroll
        for (int j = 0; j < 16; j++) {
            int col = j * 8 + c2;
            float b0v = bias[col], b1v = bias[col + 1];
            if (row0 < N_NODES)
                *(__half2*)(g_xl_h + (size_t)row0 * D + col) =
                    __floats2half2_rn(acc[j][0] + b0v, acc[j][1] + b1v);
            if (row1 < N_NODES)
                *(__half2*)(g_xl_h + (size_t)row1 * D + col) =
                    __floats2half2_rn(acc[j][2] + b0v, acc[j][3] + b1v);
        }
    } else {                                 // fp32 xr
        #pragma unroll
        for (int j = 0; j < 16; j++) {
            int col = j * 8 + c2;
            float b0v = bias[col], b1v = bias[col + 1];
            if (row0 < N_NODES)
                *(float2*)(g_xr + (size_t)row0 * D + col) = make_float2(acc[j][0] + b0v, acc[j][1] + b1v);
            if (row1 < N_NODES)
                *(float2*)(g_xr + (size_t)row1 * D + col) = make_float2(acc[j][2] + b0v, acc[j][3] + b1v);
        }
    }
}

// --------- fused edge phase: round-6 loop (no prefetch), fused pool ---------
__device__ __forceinline__ float4 h4_to_f4(uint2 u) {
    float2 a = __half22float2(*(__half2*)&u.x);
    float2 b = __half22float2(*(__half2*)&u.y);
    return make_float4(a.x, a.y, b.x, b.y);
}

__global__ void __launch_bounds__(256) k_aggregate(
    const float* __restrict__ att, const float* __restrict__ bias,
    const int* __restrict__ batch, int last)
{
    int gid  = (blockIdx.x * blockDim.x + threadIdx.x) >> 5;
    int lane = threadIdx.x & 31;
    if (gid >= N_NODES) return;

    const uint2* __restrict__ xl2 = (const uint2*)g_xl_h;
    float4 xr_v = ((const float4*)g_xr)[gid * 32 + lane];
    float4 a    = ((const float4*)att)[lane];

    float m = -INFINITY, s = 0.f;
    float ax = 0.f, ay = 0.f, az = 0.f, aw = 0.f;

    int e   = g_off[gid];
    int end = g_off[gid + 1];

    for (; e + 3 < end; e += 4) {
        int s0 = g_srcs[e],     s1 = g_srcs[e + 1];
        int s2 = g_srcs[e + 2], s3 = g_srcs[e + 3];
        float4 x0 = h4_to_f4(xl2[(size_t)s0 * 32 + lane]);
        float4 x1 = h4_to_f4(xl2[(size_t)s1 * 32 + lane]);
        float4 x2 = h4_to_f4(xl2[(size_t)s2 * 32 + lane]);
        float4 x3 = h4_to_f4(xl2[(size_t)s3 * 32 + lane]);
        float p0 = lrelu(x0.x + xr_v.x) * a.x + lrelu(x0.y + xr_v.y) * a.y +
                   lrelu(x0.z + xr_v.z) * a.z + lrelu(x0.w + xr_v.w) * a.w;
        float p1 = lrelu(x1.x + xr_v.x) * a.x + lrelu(x1.y + xr_v.y) * a.y +
                   lrelu(x1.z + xr_v.z) * a.z + lrelu(x1.w + xr_v.w) * a.w;
        float p2 = lrelu(x2.x + xr_v.x) * a.x + lrelu(x2.y + xr_v.y) * a.y +
                   lrelu(x2.z + xr_v.z) * a.z + lrelu(x2.w + xr_v.w) * a.w;
        float p3 = lrelu(x3.x + xr_v.x) * a.x + lrelu(x3.y + xr_v.y) * a.y +
                   lrelu(x3.z + xr_v.z) * a.z + lrelu(x3.w + xr_v.w) * a.w;
        p0 += __shfl_xor_sync(0xffffffffu, p0, 1);
        p1 += __shfl_xor_sync(0xffffffffu, p1, 1);
        p2 += __shfl_xor_sync(0xffffffffu, p2, 1);
        p3 += __shfl_xor_sync(0xffffffffu, p3, 1);
        p0 += __shfl_xor_sync(0xffffffffu, p0, 2);
        p1 += __shfl_xor_sync(0xffffffffu, p1, 2);
        p2 += __shfl_xor_sync(0xffffffffu, p2, 2);
        p3 += __shfl_xor_sync(0xffffffffu, p3, 2);
        float mn = fmaxf(fmaxf(m, fmaxf(p0, p1)), fmaxf(p2, p3));
        float sc = __expf(m - mn);
        float w0 = __expf(p0 - mn);
        float w1 = __expf(p1 - mn);
        float w2 = __expf(p2 - mn);
        float w3 = __expf(p3 - mn);
        s  = s * sc + (w0 + w1) + (w2 + w3);
        ax = ax * sc + (x0.x * w0 + x1.x * w1) + (x2.x * w2 + x3.x * w3);
        ay = ay * sc + (x0.y * w0 + x1.y * w1) + (x2.y * w2 + x3.y * w3);
        az = az * sc + (x0.z * w0 + x1.z * w1) + (x2.z * w2 + x3.z * w3);
        aw = aw * sc + (x0.w * w0 + x1.w * w1) + (x2.w * w2 + x3.w * w3);
        m = mn;
    }
    for (; e < end; e++) {
        int s0 = g_srcs[e];
        float4 x0 = h4_to_f4(xl2[(size_t)s0 * 32 + lane]);
        float p0 = lrelu(x0.x + xr_v.x) * a.x + lrelu(x0.y + xr_v.y) * a.y +
                   lrelu(x0.z + xr_v.z) * a.z + lrelu(x0.w + xr_v.w) * a.w;
        p0 += __shfl_xor_sync(0xffffffffu, p0, 1);
        p0 += __shfl_xor_sync(0xffffffffu, p0, 2);
        float mn = fmaxf(m, p0);
        float sc = __expf(m - mn);
        float w0 = __expf(p0 - mn);
        s  = s * sc + w0;
        ax = ax * sc + x0.x * w0;
        ay = ay * sc + x0.y * w0;
        az = az * sc + x0.z * w0;
        aw = aw * sc + x0.w * w0;
        m = mn;
    }

    float inv = 1.f / s;
    float4 bv = ((const float4*)bias)[lane];
    float4 o;
    o.x = elu(ax * inv + bv.x);
    o.y = elu(ay * inv + bv.y);
    o.z = elu(az * inv + bv.z);
    o.w = elu(aw * inv + bv.w);

    if (!last) {                             // feed next layer's GEMM
        __nv_bfloat16 h[4], l[4];
        float vv[4] = {o.x, o.y, o.z, o.w};
        #pragma unroll
        for (int j = 0; j < 4; j++) {
            h[j] = __float2bfloat16(vv[j]);
            l[j] = __float2bfloat16(vv[j] - __bfloat162float(h[j]));
        }
        ((uint2*)g_in_hi)[gid * 32 + lane] = *(const uint2*)h;
        ((uint2*)g_in_lo)[gid * 32 + lane] = *(const uint2*)l;
    } else {                                 // fused global mean pool (sum part)
        int g = batch[gid];
        float* ps = &g_psum[g * D + lane * 4];
        atomicAdd(ps + 0, o.x);
        atomicAdd(ps + 1, o.y);
        atomicAdd(ps + 2, o.z);
        atomicAdd(ps + 3, o.w);
        if (lane == 0) atomicAdd(&g_pcnt[g], 1);
    }
}

// ----------------------------- classifier -----------------------------------
__global__ void k_head(const float* __restrict__ Wout, const float* __restrict__ bout,
                       float* __restrict__ out) {
    int g = threadIdx.x;
    if (g >= N_GRAPHS) return;
    float inv = 1.f / fmaxf((float)g_pcnt[g], 1.f);
    float lg[N_CLASSES];
    #pragma unroll
    for (int c = 0; c < N_CLASSES; c++) lg[c] = bout[c];
    for (int d = 0; d < D; d++) {
        float pv = g_psum[g * D + d] * inv;
        #pragma unroll
        for (int c = 0; c < N_CLASSES; c++)
            lg[c] = fmaf(pv, Wout[d * N_CLASSES + c], lg[c]);
    }
    float mx = lg[0];
    #pragma unroll
    for (int c = 1; c < N_CLASSES; c++) mx = fmaxf(mx, lg[c]);
    float sum = 0.f;
    #pragma unroll
    for (int c = 0; c < N_CLASSES; c++) sum += expf(lg[c] - mx);
    float ls = logf(sum);
    #pragma unroll
    for (int c = 0; c < N_CLASSES; c++) out[g * N_CLASSES + c] = lg[c] - mx - ls;
}

// ----------------------------- launch --------------------------------------
extern "C" void kernel_launch(void* const* d_in, const int* in_sizes, int n_in,
                              void* d_out, int out_size) {
    const float* x    = (const float*)d_in[0];
    const int*   ei   = (const int*)d_in[1];
    const int*   batch= (const int*)d_in[2];
    const float* Wl   = (const float*)d_in[3];
    const float* bl   = (const float*)d_in[4];
    const float* Wr   = (const float*)d_in[5];
    const float* brp  = (const float*)d_in[6];
    const float* att  = (const float*)d_in[7];
    const float* bias = (const float*)d_in[8];
    const float* Wout = (const float*)d_in[9];
    const float* bout = (const float*)d_in[10];
    float* out = (float*)d_out;

    cudaFuncSetAttribute(k_gemm_mma, cudaFuncAttributeMaxDynamicSharedMemorySize, GSM_TOTAL);

    k_prep<<<(N_NODES * D / 4 + 255) / 256, 256>>>(x, ei, Wl, Wr);   // #1
    k_scan<<<1, 1024>>>();                                           // #2
    k_fill<<<(E_TOT + 255) / 256, 256>>>(ei);                        // #3

    dim3 gemm_grid((N_NODES + 127) / 128, 2);
    const int agg_blocks = (N_NODES * 32 + 255) / 256;

    for (int l = 0; l < N_LAYERS; l++) {
        k_gemm_mma<<<gemm_grid, 256, GSM_TOTAL>>>(l, bl + l * D, brp + l * D);
        k_aggregate<<<agg_blocks, 256>>>(att + l * D, bias + l * D, batch,
                                         l == N_LAYERS - 1);
    }

    k_head<<<1, 64>>>(Wout, bout, out);
}